// round 15
// baseline (speedup 1.0000x reference)
#include <cuda_runtime.h>
#include <cuda_fp16.h>
#include <math.h>

#define SQ 2048
#define BB 32
#define DD 256
#define HH 4
#define NN (SQ*BB)
#define EPSV 1e-5f
#define PITCH 40            // half units per smem row (80B, conflict-free for ldsm)
#define HSTRIDE ((size_t)NN*DD)
#define BHEAD 327680        // halfs per head in g_Bf

// ---------------- scratch --------------------------------------------------
__device__ __align__(128) __half g_W [HH*NN*DD];
__device__ __align__(128) __half g_W2[HH*NN*DD];
__device__ __align__(128) __half g_W4[HH*NN*DD];
__device__ __align__(128) __half g_Vi[HH*NN*DD];
__device__ __align__(128) __half g_kh[NN*DD];
__device__ __align__(128) __half g_qh[NN*DD];
__device__ __align__(128) __half g_vh[NN*DD];
__device__ __align__(128) float g_Mq[HH*DD*DD];
__device__ __align__(128) float g_Mk[HH*DD*DD];
__device__ __align__(128) float g_Mv[HH*DD*DD];
__device__ __align__(128) __half g_Bf[HH*BHEAD];
__device__ float g_cq[HH*DD], g_ck[HH*DD], g_cv[HH*DD], g_cw[HH*DD];
__device__ float g_ps[HH*DD*512], g_pq2[HH*DD*512];
__device__ float g_sc1[HH*DD], g_sh1[HH*DD], g_sc2[HH*DD], g_sh2[HH*DD];
__device__ float g_pm[HH*BB*16*DD], g_pd[HH*BB*16*DD], g_pw[HH*BB*16*DD];
__device__ float g_x[BB*HH*DD];
__device__ float g_h0[BB*DD], g_h1[BB*DD];

// ---------------- helpers --------------------------------------------------
__device__ __forceinline__ void mma_f16(float* c, const unsigned* a, const unsigned* b) {
    asm volatile(
        "mma.sync.aligned.m16n8k16.row.col.f32.f16.f16.f32 "
        "{%0,%1,%2,%3}, {%4,%5,%6,%7}, {%8,%9}, {%0,%1,%2,%3};"
        : "+f"(c[0]), "+f"(c[1]), "+f"(c[2]), "+f"(c[3])
        : "r"(a[0]), "r"(a[1]), "r"(a[2]), "r"(a[3]), "r"(b[0]), "r"(b[1]));
}

__device__ __forceinline__ void ldsm4(unsigned* r, unsigned addr) {
    asm volatile("ldmatrix.sync.aligned.m8n8.x4.shared.b16 {%0,%1,%2,%3}, [%4];"
        : "=r"(r[0]), "=r"(r[1]), "=r"(r[2]), "=r"(r[3]) : "r"(addr));
}

// ---------------- fp16 GEMM, tile 128x128, 4-head batched, fp16 in/out ------
// C[z] = A(fp16, opt fp32 relu(x*sc+sh)) @ Bf[z]^T + bias[z]
// grid (2, 512, HH), 256 thr (8 warps = 2m x 4n), warp tile 64x32.
// NKT = number of 32-wide K tiles (compile-time: addresses fold).
template<bool TRANS, bool STATS, int NKT>
__global__ void __launch_bounds__(256, 2)
gemm_tc(const __half* __restrict__ A0, const __half* __restrict__ A1, size_t strideA,
        const __half* __restrict__ BfG, int ldb, const float* __restrict__ biasG,
        const float* __restrict__ ascaleG, const float* __restrict__ ashiftG,
        __half* __restrict__ CG, float* __restrict__ ps, float* __restrict__ pq)
{
    __shared__ __half As[2][128][PITCH];
    __shared__ __half Bs[2][128][PITCH];
    const unsigned aBase = (unsigned)__cvta_generic_to_shared(&As[0][0][0]);
    const unsigned bBase = (unsigned)__cvta_generic_to_shared(&Bs[0][0][0]);

    const int bz = blockIdx.z;
    const __half* A0z = A0 + (size_t)bz * strideA;
    const __half* Bf  = BfG + (size_t)bz * BHEAD;
    const float*  bias = biasG + bz * DD;
    const float*  ascale = TRANS ? (ascaleG + bz * DD) : nullptr;
    const float*  ashift = TRANS ? (ashiftG + bz * DD) : nullptr;
    __half* C = CG + (size_t)bz * HSTRIDE;

    const int tid = threadIdx.x, lane = tid & 31, warp = tid >> 5;
    const int wm = warp >> 2, wn = warp & 3;      // 2 x 4
    const int g = lane >> 2, tg = lane & 3;
    const int rowBlk = blockIdx.y * 128, colBlk = blockIdx.x * 128;

    const int lrow = (lane & 7) + ((lane >> 3) & 1) * 8;
    const int lkof = ((lane >> 4) & 1) * 8;

    // hoisted per-warp ldsm bases (steady-state: base + compile-time offset)
    const unsigned aWarp = aBase + (unsigned)(((wm*64 + lrow) * PITCH + lkof) * 2);
    const unsigned bWarp = bBase + (unsigned)(((wn*32 + lrow) * PITCH + lkof) * 2);

    float acc[4][4][4];
#pragma unroll
    for (int a = 0; a < 4; ++a)
#pragma unroll
        for (int b = 0; b < 4; ++b)
#pragma unroll
            for (int c = 0; c < 4; ++c) acc[a][b][c] = 0.f;

    uint4 Arf[2], Brf[2];

    auto ldg_tile = [&](int kt) {
        int k0 = kt * 32;
        const __half* src = A0z; int kb = k0;
        if (A1 != nullptr && k0 >= DD) { src = A1; kb = k0 - DD; }
#pragma unroll
        for (int p = 0; p < 2; ++p) {
            int idx = tid + p * 256, r = idx >> 2, c8 = (idx & 3) * 8;
            Arf[p] = *reinterpret_cast<const uint4*>(&src[(size_t)(rowBlk + r) * DD + kb + c8]);
            Brf[p] = *reinterpret_cast<const uint4*>(&Bf[(size_t)(colBlk + r) * ldb + k0 + c8]);
        }
    };

    auto sts_tile = [&](int buf, int kt) {
        int k0 = kt * 32;
        int kb = (A1 != nullptr && k0 >= DD) ? (k0 - DD) : k0;
#pragma unroll
        for (int p = 0; p < 2; ++p) {
            int idx = tid + p * 256, r = idx >> 2, c8 = (idx & 3) * 8;
            if (TRANS) {
                __half2* hp = reinterpret_cast<__half2*>(&Arf[p]);
                float fr[8];
#pragma unroll
                for (int j = 0; j < 4; ++j) {
                    float2 t = __half22float2(hp[j]);
                    fr[2*j] = t.x; fr[2*j + 1] = t.y;
                }
#pragma unroll
                for (int j = 0; j < 8; ++j) {
                    int ch = kb + c8 + j;
                    fr[j] = fmaxf(fr[j] * ascale[ch] + ashift[ch], 0.f);
                }
                uint4 o;
                __half2 h0 = __floats2half2_rn(fr[0], fr[1]);
                __half2 h1 = __floats2half2_rn(fr[2], fr[3]);
                __half2 h2 = __floats2half2_rn(fr[4], fr[5]);
                __half2 h3 = __floats2half2_rn(fr[6], fr[7]);
                o.x = *reinterpret_cast<unsigned*>(&h0);
                o.y = *reinterpret_cast<unsigned*>(&h1);
                o.z = *reinterpret_cast<unsigned*>(&h2);
                o.w = *reinterpret_cast<unsigned*>(&h3);
                *reinterpret_cast<uint4*>(&As[buf][r][c8]) = o;
            } else {
                *reinterpret_cast<uint4*>(&As[buf][r][c8]) = Arf[p];
            }
            *reinterpret_cast<uint4*>(&Bs[buf][r][c8]) = Brf[p];
        }
    };

    auto compute = [&](int buf) {
        const unsigned aB = aWarp + (unsigned)(buf * 128 * PITCH * 2);
        const unsigned bB = bWarp + (unsigned)(buf * 128 * PITCH * 2);
#pragma unroll
        for (int kk = 0; kk < 2; ++kk) {
            const int kp = kk * 16 * 2;
            unsigned aF[4][4], bF[2][4];
#pragma unroll
            for (int mi = 0; mi < 4; ++mi)
                ldsm4(aF[mi], aB + (unsigned)(mi * 16 * PITCH * 2 + kp));
#pragma unroll
            for (int p = 0; p < 2; ++p)
                ldsm4(bF[p], bB + (unsigned)(p * 16 * PITCH * 2 + kp));
#pragma unroll
            for (int mi = 0; mi < 4; ++mi)
#pragma unroll
                for (int ni = 0; ni < 4; ++ni) {
                    const int p = ni >> 1, s = ni & 1;
                    unsigned bb[2] = {bF[p][s], bF[p][s + 2]};
                    mma_f16(acc[mi][ni], aF[mi], bb);
                }
        }
    };

    ldg_tile(0);
    sts_tile(0, 0);
#pragma unroll 2
    for (int kt = 0; kt < NKT; ++kt) {
        __syncthreads();
        if (kt + 1 < NKT) ldg_tile(kt + 1);
        compute(kt & 1);
        if (kt + 1 < NKT) sts_tile((kt + 1) & 1, kt + 1);
    }

    // ---- epilogue: bias + fp16 store + fused fp32 stats ----
#pragma unroll
    for (int ni = 0; ni < 4; ++ni) {
        int c = colBlk + wn*32 + ni*8 + tg*2;
        float b0 = bias[wn*32 + ni*8 + tg*2 + colBlk];
        float b1 = bias[wn*32 + ni*8 + tg*2 + colBlk + 1];
#pragma unroll
        for (int mi = 0; mi < 4; ++mi) {
            acc[mi][ni][0] += b0; acc[mi][ni][1] += b1;
            acc[mi][ni][2] += b0; acc[mi][ni][3] += b1;
            int r = rowBlk + wm*64 + mi*16 + g;
            __half2 h0 = __floats2half2_rn(acc[mi][ni][0], acc[mi][ni][1]);
            __half2 h1 = __floats2half2_rn(acc[mi][ni][2], acc[mi][ni][3]);
            *reinterpret_cast<unsigned*>(&C[(size_t)r * DD + c]) =
                *reinterpret_cast<unsigned*>(&h0);
            *reinterpret_cast<unsigned*>(&C[(size_t)(r + 8) * DD + c]) =
                *reinterpret_cast<unsigned*>(&h1);
        }
    }
    if (STATS) {
        __syncthreads();
        float* sS = (float*)&As[0][0][0];    // smem reuse: 2x256 floats
        float* sQ = sS + 256;
#pragma unroll
        for (int ni = 0; ni < 4; ++ni)
#pragma unroll
            for (int j = 0; j < 2; ++j) {
                float s = 0.f, q = 0.f;
#pragma unroll
                for (int mi = 0; mi < 4; ++mi) {
                    float a = acc[mi][ni][j], b = acc[mi][ni][j + 2];
                    s += a + b; q += a*a + b*b;
                }
#pragma unroll
                for (int off = 4; off < 32; off <<= 1) {
                    s += __shfl_xor_sync(0xffffffffu, s, off);
                    q += __shfl_xor_sync(0xffffffffu, q, off);
                }
                if (g == 0) {
                    int ch = wn*32 + ni*8 + tg*2 + j;       // 0..127
                    sS[wm*128 + ch] = s;
                    sQ[wm*128 + ch] = q;
                }
            }
        __syncthreads();
        if (tid < 128) {
            float s = sS[tid] + sS[128 + tid];
            float q = sQ[tid] + sQ[128 + tid];
            size_t o = ((size_t)bz * DD + colBlk + tid) * 512 + blockIdx.y;
            ps[o] = s; pq[o] = q;
        }
    }
}

// ---------------- q/k/v fp32 -> fp16 ----------------------------------------
__global__ void conv_qkv(const float* __restrict__ q, const float* __restrict__ k,
                         const float* __restrict__ v) {
    int z = blockIdx.y;
    const float* src = (z == 0) ? q : (z == 1) ? k : v;
    __half* dst = (z == 0) ? g_qh : (z == 1) ? g_kh : g_vh;
    size_t i = ((size_t)blockIdx.x * 256 + threadIdx.x) * 4;
    float4 f = *reinterpret_cast<const float4*>(&src[i]);
    __half2 h0 = __floats2half2_rn(f.x, f.y);
    __half2 h1 = __floats2half2_rn(f.z, f.w);
    *reinterpret_cast<uint2*>(&dst[i]) =
        make_uint2(*reinterpret_cast<unsigned*>(&h0), *reinterpret_cast<unsigned*>(&h1));
}

// ---------------- B pre-convert (all heads) + cw -----------------------------
__global__ void conv_b(const float* __restrict__ Mk, const float* __restrict__ Mq,
                       const float* __restrict__ wl1, const float* __restrict__ wl2,
                       const float* __restrict__ Mv, const float* __restrict__ ckh,
                       const float* __restrict__ cqh, float* __restrict__ cwh) {
    int z = blockIdx.y;
    int gid = blockIdx.x * 256 + threadIdx.x;      // 0..327679 within head
    int mo = z * DD * DD, vo = z * DD;
    if (gid < 256) cwh[vo + gid] = ckh[vo + gid] - cqh[vo + gid];
    float v;
    if (gid < 131072) {                            // [Mk | -Mq]  256 x 512
        int n = gid >> 9, kk = gid & 511;
        v = (kk < DD) ? Mk[mo + n*DD + kk] : -Mq[mo + n*DD + kk - DD];
    } else if (gid < 196608) v = wl1[mo + gid - 131072];
    else if   (gid < 262144) v = wl2[mo + gid - 196608];
    else                     v = Mv [mo + gid - 262144];
    g_Bf[(size_t)z * BHEAD + gid] = __float2half(v);
}

// ---------------- BN stage-2 (all heads) -------------------------------------
__global__ void bn_stats2(const float* __restrict__ gamma, const float* __restrict__ beta,
                          float* __restrict__ sc, float* __restrict__ sh) {
    int d = blockIdx.x, h = blockIdx.y, t = threadIdx.x;
    size_t base = ((size_t)h * DD + d) * 512;
    float s  = g_ps [base + t] + g_ps [base + 256 + t];
    float qq = g_pq2[base + t] + g_pq2[base + 256 + t];
    __shared__ float ss[256], sq[256];
    ss[t] = s; sq[t] = qq; __syncthreads();
    for (int o = 128; o > 0; o >>= 1) {
        if (t < o) { ss[t] += ss[t + o]; sq[t] += sq[t + o]; }
        __syncthreads();
    }
    if (t == 0) {
        float mean = ss[0] / (float)NN;
        float var  = sq[0] / (float)NN - mean * mean;
        float is   = rsqrtf(fmaxf(var, 0.f) + EPSV);
        float scale = gamma[h*DD + d] * is;
        sc[h*DD + d] = scale; sh[h*DD + d] = beta[h*DD + d] - mean * scale;
    }
}

// ---------------- softmax over S fused with weighted-V sum (all heads) -------
__global__ void smax_part(const __half* __restrict__ W4, const __half* __restrict__ V) {
    int d = threadIdx.x, ch = blockIdx.x, b = blockIdx.y, z = blockIdx.z;
    size_t base = (size_t)z * HSTRIDE + ((size_t)ch * 128 * BB + b) * DD + d;
    float m = -1e30f, den = 0.f, wv = 0.f;
#pragma unroll 2
    for (int s = 0; s < 128; ++s) {
        size_t o = base + (size_t)s * BB * DD;
        float w = __half2float(W4[o]), vv = __half2float(V[o]);
        float nm = fmaxf(m, w);
        float f = __expf(m - nm), e = __expf(w - nm);
        den = den * f + e; wv = wv * f + e * vv; m = nm;
    }
    size_t o = (((size_t)z * BB + b) * 16 + ch) * DD + d;
    g_pm[o] = m; g_pd[o] = den; g_pw[o] = wv;
}

__global__ void smax_comb() {
    int d = threadIdx.x, b = blockIdx.x, z = blockIdx.y;
    float m = -1e30f, den = 0.f, wv = 0.f;
#pragma unroll
    for (int c = 0; c < 16; ++c) {
        size_t o = (((size_t)z * BB + b) * 16 + c) * DD + d;
        float m2 = g_pm[o], nm = fmaxf(m, m2);
        float f = __expf(m - nm), e = __expf(m2 - nm);
        den = den * f + g_pd[o] * e;
        wv  = wv  * f + g_pw[o] * e;
        m = nm;
    }
    g_x[b * (HH * DD) + z * DD + d] = wv / den;
}

// ---------------- composition of chained projections ------------------------
__global__ void compose_mat(const float* __restrict__ wq, const float* __restrict__ wk,
                            const float* __restrict__ wv, float* __restrict__ Mq,
                            float* __restrict__ Mk, float* __restrict__ Mv, int step) {
    const float* Wb; float* Mb;
    if (blockIdx.z == 0)      { Wb = wq; Mb = Mq; }
    else if (blockIdx.z == 1) { Wb = wk; Mb = Mk; }
    else                      { Wb = wv; Mb = Mv; }
    const float* Wi  = Wb + step * DD * DD;
    const float* Min = Mb + (step - 1) * DD * DD;
    float* Mout      = Mb + step * DD * DD;
    __shared__ float row[DD];
    int d = blockIdx.x, e = threadIdx.x;
    row[e] = Wi[d * DD + e]; __syncthreads();
    float acc = 0.f;
#pragma unroll 8
    for (int c = 0; c < DD; ++c) acc += row[c] * Min[c * DD + e];
    Mout[d * DD + e] = acc;
}

__global__ void compose_bias(const float* __restrict__ wq, const float* __restrict__ wk,
                             const float* __restrict__ wv, const float* __restrict__ bq,
                             const float* __restrict__ bk, const float* __restrict__ bv,
                             float* __restrict__ cq, float* __restrict__ ck,
                             float* __restrict__ cv, int step) {
    const float* Wb; const float* bb; float* cc;
    if (blockIdx.z == 0)      { Wb = wq; bb = bq; cc = cq; }
    else if (blockIdx.z == 1) { Wb = wk; bb = bk; cc = ck; }
    else                      { Wb = wv; bb = bv; cc = cv; }
    int d = blockIdx.x, t = threadIdx.x;
    float a = Wb[step*DD*DD + d*DD + t] * cc[(step-1)*DD + t];
#pragma unroll
    for (int off = 16; off > 0; off >>= 1) a += __shfl_xor_sync(0xffffffffu, a, off);
    __shared__ float w[8];
    if ((t & 31) == 0) w[t >> 5] = a;
    __syncthreads();
    if (t == 0) {
        float s = 0.f;
#pragma unroll
        for (int i = 0; i < 8; ++i) s += w[i];
        cc[step*DD + d] = bb[step*DD + d] + s;
    }
}

// ---------------- tiny MLP ---------------------------------------------------
__global__ void mlp_gemm(const float* __restrict__ in, int K, const float* __restrict__ W,
                         const float* __restrict__ bias, float* __restrict__ out, int dorelu) {
    __shared__ float sA[1024];
    int b = blockIdx.x, d = threadIdx.x;
    for (int i = d; i < K; i += blockDim.x) sA[i] = in[b * K + i];
    __syncthreads();
    float acc = bias[d];
    const float* w = W + (size_t)d * K;
#pragma unroll 8
    for (int c = 0; c < K; ++c) acc += sA[c] * w[c];
    if (dorelu) acc = fmaxf(acc, 0.f);
    out[b * DD + d] = acc;
}

// ---------------- launch -----------------------------------------------------
extern "C" void kernel_launch(void* const* d_in, const int* in_sizes, int n_in,
                              void* d_out, int out_size) {
    const float* q   = (const float*)d_in[0];
    const float* k   = (const float*)d_in[1];
    const float* v   = (const float*)d_in[2];
    const float* wq  = (const float*)d_in[3];
    const float* bq  = (const float*)d_in[4];
    const float* wk  = (const float*)d_in[5];
    const float* bk  = (const float*)d_in[6];
    const float* wv  = (const float*)d_in[7];
    const float* bv  = (const float*)d_in[8];
    const float* g1  = (const float*)d_in[9];
    const float* be1 = (const float*)d_in[10];
    const float* wl1 = (const float*)d_in[11];
    const float* bl1 = (const float*)d_in[12];
    const float* g2  = (const float*)d_in[13];
    const float* be2 = (const float*)d_in[14];
    const float* wl2 = (const float*)d_in[15];
    const float* bl2 = (const float*)d_in[16];
    const float* mw0 = (const float*)d_in[17];
    const float* mb0 = (const float*)d_in[18];
    const float* mw1 = (const float*)d_in[19];
    const float* mb1 = (const float*)d_in[20];
    const float* mw2 = (const float*)d_in[21];
    const float* mb2 = (const float*)d_in[22];
    float* out = (float*)d_out;

    float *Mq, *Mk, *Mv, *cq, *ck, *cv, *cw;
    float *sc1, *sh1, *sc2, *sh2, *X, *H0, *H1, *PS, *PQ;
    __half *Bf, *W, *W2, *W4, *Vi, *kh, *qh, *vh;
    cudaGetSymbolAddress((void**)&Mq,  g_Mq);
    cudaGetSymbolAddress((void**)&Mk,  g_Mk);
    cudaGetSymbolAddress((void**)&Mv,  g_Mv);
    cudaGetSymbolAddress((void**)&cq,  g_cq);
    cudaGetSymbolAddress((void**)&ck,  g_ck);
    cudaGetSymbolAddress((void**)&cv,  g_cv);
    cudaGetSymbolAddress((void**)&cw,  g_cw);
    cudaGetSymbolAddress((void**)&W,   g_W);
    cudaGetSymbolAddress((void**)&W2,  g_W2);
    cudaGetSymbolAddress((void**)&W4,  g_W4);
    cudaGetSymbolAddress((void**)&Vi,  g_Vi);
    cudaGetSymbolAddress((void**)&kh,  g_kh);
    cudaGetSymbolAddress((void**)&qh,  g_qh);
    cudaGetSymbolAddress((void**)&vh,  g_vh);
    cudaGetSymbolAddress((void**)&sc1, g_sc1);
    cudaGetSymbolAddress((void**)&sh1, g_sh1);
    cudaGetSymbolAddress((void**)&sc2, g_sc2);
    cudaGetSymbolAddress((void**)&sh2, g_sh2);
    cudaGetSymbolAddress((void**)&X,   g_x);
    cudaGetSymbolAddress((void**)&H0,  g_h0);
    cudaGetSymbolAddress((void**)&H1,  g_h1);
    cudaGetSymbolAddress((void**)&PS,  g_ps);
    cudaGetSymbolAddress((void**)&PQ,  g_pq2);
    cudaGetSymbolAddress((void**)&Bf,  g_Bf);

    const size_t MB = (size_t)DD * DD * sizeof(float);
    const size_t VB = (size_t)DD * sizeof(float);

    cudaMemcpyAsync(Mq, wq, MB, cudaMemcpyDeviceToDevice);
    cudaMemcpyAsync(Mk, wk, MB, cudaMemcpyDeviceToDevice);
    cudaMemcpyAsync(Mv, wv, MB, cudaMemcpyDeviceToDevice);
    cudaMemcpyAsync(cq, bq, VB, cudaMemcpyDeviceToDevice);
    cudaMemcpyAsync(ck, bk, VB, cudaMemcpyDeviceToDevice);
    cudaMemcpyAsync(cv, bv, VB, cudaMemcpyDeviceToDevice);

    // prologue
    conv_qkv<<<dim3(NN*DD/1024, 3), 256>>>(q, k, v);
    for (int s = 1; s < HH; ++s) {
        compose_mat <<<dim3(DD,1,3), DD>>>(wq, wk, wv, Mq, Mk, Mv, s);
        compose_bias<<<dim3(DD,1,3), DD>>>(wq, wk, wv, bq, bk, bv, cq, ck, cv, s);
    }
    conv_b<<<dim3(1280, HH), 256>>>(Mk, Mq, wl1, wl2, Mv, ck, cq, cw);

    dim3 gg(DD / 128, NN / 128, HH);   // (2, 512, 4)

    // W = k0@Mk^T - q0@Mq^T + cw (+ fused BN1 partials)   [all heads]
    gemm_tc<false,true,16><<<gg, 256>>>(
        kh, qh, 0, Bf, 512, cw, nullptr, nullptr, W, PS, PQ);
    // Vi = v0 @ Mv^T + cv   [all heads, independent]
    gemm_tc<false,false,8><<<gg, 256>>>(
        vh, nullptr, 0, Bf + 262144, 256, cv, nullptr, nullptr, Vi, PS, PQ);
    bn_stats2<<<dim3(DD, HH), 256>>>(g1, be1, sc1, sh1);
    // W2 = relu(bn(W)) @ wl1^T + bl1 (+ fused BN2 partials)
    gemm_tc<true,true,8><<<gg, 256>>>(
        W, nullptr, HSTRIDE, Bf + 131072, 256, bl1, sc1, sh1, W2, PS, PQ);
    bn_stats2<<<dim3(DD, HH), 256>>>(g2, be2, sc2, sh2);
    // W4 = relu(bn(W2)) @ wl2^T + bl2
    gemm_tc<true,false,8><<<gg, 256>>>(
        W2, nullptr, HSTRIDE, Bf + 196608, 256, bl2, sc2, sh2, W4, PS, PQ);
    // softmax over S + weighted-V reduction
    smax_part<<<dim3(16, BB, HH), 256>>>(W4, Vi);
    smax_comb<<<dim3(BB, HH), 256>>>();

    mlp_gemm<<<BB, DD>>>(X,  HH * DD, mw0, mb0, H0, 1);
    mlp_gemm<<<BB, DD>>>(H0, DD,      mw1, mb1, H1, 1);
    mlp_gemm<<<BB, DD>>>(H1, DD,      mw2, mb2, out, 0);
    (void)in_sizes; (void)n_in; (void)out_size;
}